// round 15
// baseline (speedup 1.0000x reference)
#include <cuda_runtime.h>
#include <cstdint>

#define B 8
#define O 2048
#define Q 2048
#define D 128
#define KT 10      // expansion terms k = 0..9 (remainder <= 7.5e-7 rel at x<=1)
#define GS 12      // g_s row stride (floats), 16B-aligned
#define NCH 64     // obs chunks per batch
#define CH 32      // obs rows per chunk

// Scratch (allocation-free rule: device globals; zero-initialized at load).
// g_M / g_msum_in / g_done are consumed AND reset inside k_moments' last-CTA
// epilogue, so every kernel_launch invocation starts from zeros.
__device__ float g_M[B * KT * D];        // accumulated moments
__device__ float g_msum_in[B * KT];      // accumulated weight sums
__device__ unsigned int g_done[B];       // per-batch completion counters
__device__ __align__(16) float g_Mp[B * KT * D];   // projected moments
__device__ __align__(16) float g_msum[B * KT];     // weight-sum moments (for C)

__constant__ float c_invk[KT] = {0.f, 1.f, 1.f/2, 1.f/3, 1.f/4, 1.f/5, 1.f/6,
                                 1.f/7, 1.f/8, 1.f/9};

// PDL: wait for the upstream grid's memory to be visible (sm_90+ PTX).
__device__ __forceinline__ void grid_dep_wait() {
    asm volatile("griddepcontrol.wait;" ::: "memory");
}

// ---------------------------------------------------------------------------
// Kernel A: per (batch, 32-obs chunk) moments, reduced across CTAs via RED,
// WITH the projection (old kernel B) fused in via last-CTA-per-batch.
//   g_k(o) = mask_o * exp(-0.5*c2*t_o^2) * (c2*t_o)^k / k!
//   g_M[b][k][e] += sum_o g_k(o)*emb[o][e] ;  g_msum_in[b][k] += sum_o g_k(o)
// The 64th finisher of each batch computes Mp[b][k][e'] = W[e'][:]·M[b][k][:],
// publishes g_Mp/g_msum, and resets all accumulators for the next replay.
// 512 CTAs x 256 threads, A body identical to the best-measured R13 shape.
// ---------------------------------------------------------------------------
__global__ __launch_bounds__(256) void k_moments(
    const float* __restrict__ obs_emb,
    const float* __restrict__ obs_times,
    const float* __restrict__ obs_mask,
    const float* __restrict__ log_sigma,
    const float* __restrict__ W_proj)
{
    __shared__ __align__(16) float g_s[CH * GS];   // 10 used, pad to 12
    __shared__ __align__(16) float red[KT * D];
    __shared__ int s_last;

    const int tid = threadIdx.x;
    const int c   = blockIdx.x;
    const int b   = blockIdx.y;
    const int o0  = c * CH;
    const float c2 = __expf(-2.0f * log_sigma[0]);   // 1/sigma^2

    // Phase 1: 32 threads compute g_k rows
    if (tid < CH) {
        const int o = o0 + tid;
        const float t  = obs_times[b * O + o];
        const float mk = obs_mask[b * O + o];
        const float xx = c2 * t;
        float g = mk * __expf(-0.5f * c2 * t * t);
        g_s[tid * GS + 0] = g;
#pragma unroll
        for (int k = 1; k < KT; ++k) {
            g *= xx * c_invk[k];
            g_s[tid * GS + k] = g;
        }
    }
    __syncthreads();

    // ms partials -> atomic accumulate
    if (tid < KT) {
        float s = 0.0f;
#pragma unroll
        for (int o = 0; o < CH; ++o) s += g_s[o * GS + tid];
        atomicAdd(&g_msum_in[b * KT + tid], s);
    }

    // Phase 2: accumulate moments over 16 rows per thread, loads in-loop.
    const int e    = tid & 127;
    const int half = tid >> 7;
    float acc[KT];
#pragma unroll
    for (int k = 0; k < KT; ++k) acc[k] = 0.0f;

    const float* ebase = obs_emb + ((size_t)(b * O) + o0 + half * 16) * D + e;
    const float* gbase = g_s + half * 16 * GS;
#pragma unroll
    for (int oo = 0; oo < 16; ++oo) {
        const float xv = ebase[(size_t)oo * D];
        const float4 ga = *(const float4*)(gbase + oo * GS + 0);
        const float4 gb = *(const float4*)(gbase + oo * GS + 4);
        const float2 gc = *(const float2*)(gbase + oo * GS + 8);
        acc[0] = fmaf(ga.x, xv, acc[0]);   acc[1] = fmaf(ga.y, xv, acc[1]);
        acc[2] = fmaf(ga.z, xv, acc[2]);   acc[3] = fmaf(ga.w, xv, acc[3]);
        acc[4] = fmaf(gb.x, xv, acc[4]);   acc[5] = fmaf(gb.y, xv, acc[5]);
        acc[6] = fmaf(gb.z, xv, acc[6]);   acc[7] = fmaf(gb.w, xv, acc[7]);
        acc[8] = fmaf(gc.x, xv, acc[8]);   acc[9] = fmaf(gc.y, xv, acc[9]);
    }

    // combine the two halves via SMEM, then RED.ADD into g_M
    if (half == 1) {
#pragma unroll
        for (int k = 0; k < KT; ++k) red[k * D + e] = acc[k];
    }
    __syncthreads();
    if (half == 0) {
        float* dst = g_M + (size_t)(b * KT) * D + e;
        const float* r0 = red + e;
#pragma unroll
        for (int k = 0; k < KT; ++k)
            atomicAdd(dst + k * D, acc[k] + r0[k * D]);
    }

    // ---- last-CTA-per-batch: fused projection (old kernel B) ----
    __threadfence();   // make this CTA's REDs visible before signaling
    if (tid == 0)
        s_last = (atomicAdd(&g_done[b], 1u) == NCH - 1) ? 1 : 0;
    __syncthreads();
    if (s_last == 0) return;

    // This is the 64th (last) CTA of batch b: all other REDs are visible.
    float* m_s = red;   // reuse SMEM (KT*D floats = 5KB)
    float* mb = g_M + (size_t)(b * KT) * D;
#pragma unroll
    for (int i = 0; i < 5; ++i) {
        const int idx = tid + i * 256;          // 0..1279
        m_s[idx] = mb[idx];
        mb[idx] = 0.0f;                          // restore zero state
    }
    if (tid < KT) {
        g_msum[b * KT + tid] = g_msum_in[b * KT + tid];
        g_msum_in[b * KT + tid] = 0.0f;          // restore zero state
    }
    if (tid == 0) g_done[b] = 0;                 // restore counter
    __syncthreads();

    // Projection: Mp[b][k][e'] = sum_e W[e'][e] * m[k][e]; 5 outputs/thread.
#pragma unroll
    for (int i = 0; i < 5; ++i) {
        const int idx = tid + i * 256;
        const int k  = idx >> 7;
        const int ep = idx & 127;
        const float4* wrow = (const float4*)(W_proj + (size_t)ep * D);
        const float4* mrow = (const float4*)(m_s + k * D);
        float dot = 0.0f;
#pragma unroll
        for (int j = 0; j < D / 4; ++j) {
            const float4 w4 = wrow[j];
            const float4 m4 = mrow[j];
            dot += w4.x * m4.x + w4.y * m4.y + w4.z * m4.z + w4.w * m4.w;
        }
        g_Mp[(size_t)(b * KT) * D + idx] = dot;
    }
}

// ---------------------------------------------------------------------------
// Kernel C: combine. out[q][e'] = (sum_k f_k(q) Mp[k][e']) / (sum_k f_k msum[k]) + b[e']
// Thread owns 4 e-cols and FOUR q's with interleaved f-chains. PDL preamble
// before the wait. 512 CTAs (32 q each), 256 threads.
// ---------------------------------------------------------------------------
__global__ __launch_bounds__(256) void k_combine(
    const float* __restrict__ query_times,
    const float* __restrict__ log_sigma,
    const float* __restrict__ b_proj,
    float* __restrict__ out)
{
    const int tid = threadIdx.x;
    const int b   = blockIdx.y;
    const int q0  = blockIdx.x * 32;
    const int e   = (tid & 31) * 4;
    const int qh  = tid >> 5;          // 0..7, 4 q's each

    // ---- preamble (independent of A's output) ----
    const float* qtp = query_times + b * Q + q0 + qh * 4;
    float qt[4], f[4];
#pragma unroll
    for (int j = 0; j < 4; ++j) qt[j] = qtp[j];
    const float c2 = __expf(-2.0f * log_sigma[0]);
    const float4 bp = *(const float4*)&b_proj[e];
#pragma unroll
    for (int j = 0; j < 4; ++j) f[j] = __expf(-0.5f * c2 * qt[j] * qt[j]);

    grid_dep_wait();   // A's g_Mp / g_msum now visible

    float4 mp[KT];
    float  ms[KT];
    const float* mpb = g_Mp + (size_t)b * KT * D + e;
    const float* msb = g_msum + b * KT;
#pragma unroll
    for (int k = 0; k < KT; ++k) {
        mp[k] = *(const float4*)(mpb + k * D);
        ms[k] = msb[k];
    }

    float4 n[4];
    float  d[4];
#pragma unroll
    for (int j = 0; j < 4; ++j) {
        n[j].x = f[j] * mp[0].x; n[j].y = f[j] * mp[0].y;
        n[j].z = f[j] * mp[0].z; n[j].w = f[j] * mp[0].w;
        d[j] = f[j] * ms[0];
    }
#pragma unroll
    for (int k = 1; k < KT; ++k) {
#pragma unroll
        for (int j = 0; j < 4; ++j) {
            f[j] *= qt[j];
            n[j].x = fmaf(f[j], mp[k].x, n[j].x);
            n[j].y = fmaf(f[j], mp[k].y, n[j].y);
            n[j].z = fmaf(f[j], mp[k].z, n[j].z);
            n[j].w = fmaf(f[j], mp[k].w, n[j].w);
            d[j] = fmaf(f[j], ms[k], d[j]);
        }
    }
    float* ob = out + ((size_t)(b * Q) + q0 + qh * 4) * D + e;
#pragma unroll
    for (int j = 0; j < 4; ++j) {
        const float inv = __fdividef(1.0f, fmaxf(d[j], 1e-8f));
        float4 v;
        v.x = fmaf(n[j].x, inv, bp.x);
        v.y = fmaf(n[j].y, inv, bp.y);
        v.z = fmaf(n[j].z, inv, bp.z);
        v.w = fmaf(n[j].w, inv, bp.w);
        *(float4*)(ob + (size_t)j * D) = v;
    }
}

// ---------------------------------------------------------------------------
extern "C" void kernel_launch(void* const* d_in, const int* in_sizes, int n_in,
                              void* d_out, int out_size) {
    const float* obs_emb     = (const float*)d_in[0];
    const float* obs_times   = (const float*)d_in[1];
    const float* query_times = (const float*)d_in[2];
    const float* obs_mask    = (const float*)d_in[3];
    const float* log_sigma   = (const float*)d_in[4];
    const float* W_proj      = (const float*)d_in[5];
    const float* b_proj      = (const float*)d_in[6];
    float* out = (float*)d_out;

    // A (with fused projection): normal launch
    dim3 gA(NCH, B);
    k_moments<<<gA, 256>>>(obs_emb, obs_times, obs_mask, log_sigma, W_proj);

    // C: programmatic dependent launch (overlap ramp with A's drain)
    cudaLaunchAttribute attr[1];
    attr[0].id = cudaLaunchAttributeProgrammaticStreamSerialization;
    attr[0].val.programmaticStreamSerializationAllowed = 1;

    cudaLaunchConfig_t cfg = {};
    cfg.gridDim  = dim3(Q / 32, B);
    cfg.blockDim = dim3(256);
    cfg.stream   = 0;
    cfg.attrs    = attr;
    cfg.numAttrs = 1;
    cudaLaunchKernelEx(&cfg, k_combine, query_times, log_sigma, b_proj, out);
}